// round 6
// baseline (speedup 1.0000x reference)
#include <cuda_runtime.h>

// Problem constants (fixed by the reference).
#define N_IN      262144         // INPUT_LAYER
#define HIDDEN    3
#define LAYERS    120
#define NCHAIN    (LAYERS - 1)   // 119
#define OUTPUTS   18

#define BLOCKS    256
#define THREADS   256
// (N_IN/4) / (BLOCKS*THREADS) == 1 : exactly one float4 per thread per W0 row.

#define LOG2E_X2  2.8853900817779268f   // 2/ln(2)

// Scratch (no allocations allowed).
__device__ float  g_part[BLOCKS * 3];   // per-block partial dot products
__device__ float4 g_H[LAYERS];          // stacked hidden states (xyz used)

// tanh from PRE-SCALED argument t = 2x/ln2:
//   e = 2^t = e^{2x};  tanh = 1 - 2/(e+1).
// Saturation-safe: e=inf -> 1; e=0 -> -1. Chain EX2+FADD+RCP+FMA ~= 40cyc.
__device__ __forceinline__ float tanh_scaled(float t) {
    float e, r;
    asm("ex2.approx.f32 %0, %1;" : "=f"(e) : "f"(t));
    float den = e + 1.0f;
    asm("rcp.approx.f32 %0, %1;" : "=f"(r) : "f"(den));
    return fmaf(-2.0f, r, 1.0f);
}

// ---------------- Kernel A: the HBM-bound input projection -----------------
__global__ __launch_bounds__(THREADS)
void dqn_phase1_kernel(const float* __restrict__ x,
                       const float* __restrict__ W0)     // (3, 262144)
{
    __shared__ float wsum[3][8];

    const int tid = threadIdx.x;
    const int g   = blockIdx.x * THREADS + tid;

    const float4 xv = reinterpret_cast<const float4*>(x)[g];
    const float4 a0 = reinterpret_cast<const float4*>(W0)[g];
    const float4 a1 = reinterpret_cast<const float4*>(W0 + N_IN)[g];
    const float4 a2 = reinterpret_cast<const float4*>(W0 + 2 * N_IN)[g];

    float s0 = a0.x * xv.x + a0.y * xv.y + a0.z * xv.z + a0.w * xv.w;
    float s1 = a1.x * xv.x + a1.y * xv.y + a1.z * xv.z + a1.w * xv.w;
    float s2 = a2.x * xv.x + a2.y * xv.y + a2.z * xv.z + a2.w * xv.w;

    #pragma unroll
    for (int off = 16; off > 0; off >>= 1) {
        s0 += __shfl_down_sync(0xFFFFFFFFu, s0, off);
        s1 += __shfl_down_sync(0xFFFFFFFFu, s1, off);
        s2 += __shfl_down_sync(0xFFFFFFFFu, s2, off);
    }
    const int wid = tid >> 5, lid = tid & 31;
    if (lid == 0) { wsum[0][wid] = s0; wsum[1][wid] = s1; wsum[2][wid] = s2; }
    __syncthreads();

    if (tid == 0) {
        float b0 = 0.f, b1 = 0.f, b2 = 0.f;
        #pragma unroll
        for (int w = 0; w < 8; ++w) {
            b0 += wsum[0][w]; b1 += wsum[1][w]; b2 += wsum[2][w];
        }
        g_part[blockIdx.x * 3 + 0] = b0;
        g_part[blockIdx.x * 3 + 1] = b1;
        g_part[blockIdx.x * 3 + 2] = b2;
    }
    // Kernel boundary = fence; no atomics, no spin.
}

// ---------------- Kernel B: reduce + serial chain + head -------------------
__global__ __launch_bounds__(THREADS, 1)   // open the register budget
void dqn_tail_kernel(const float* __restrict__ bih0,   // (3,)
                     const float* __restrict__ bhh0,   // (3,)
                     const float* __restrict__ Wl,     // (119, 3, 3)
                     const float* __restrict__ bil,    // (119, 3)
                     const float* __restrict__ bhl,    // (119, 3)
                     const float* __restrict__ Wh,     // (18, 120)
                     const float* __restrict__ bh,     // (18,)
                     float* __restrict__ out)          // (3, 18)
{
    // Chain weights packed 12 floats/layer (9 W + 3 fused bias), pre-scaled by
    // 2/ln2 so each layer's tanh skips its leading FMUL. One pad layer so the
    // software-pipeline prefetch of layer l+1 never reads OOB.
    __shared__ float4 sP[(NCHAIN + 1) * 3];
    __shared__ float  sWh[OUTPUTS * LAYERS];
    __shared__ float  sBh[OUTPUTS];

    const int tid = threadIdx.x;

    // --- Preload + repack + prescale (warps 0-7 cooperate; DRAM latency) ---
    float* sPf = reinterpret_cast<float*>(sP);
    for (int i = tid; i < NCHAIN * 12; i += THREADS) {
        const int l = i / 12, k = i - l * 12;
        const float v = (k < 9) ? Wl[l * 9 + k]
                                : bil[l * 3 + (k - 9)] + bhl[l * 3 + (k - 9)];
        sPf[i] = v * LOG2E_X2;
    }
    if (tid < 12) sPf[NCHAIN * 12 + tid] = 0.f;     // pad layer (never used)
    for (int i = tid; i < OUTPUTS * LAYERS; i += THREADS) sWh[i] = Wh[i];
    if (tid < OUTPUTS) sBh[tid] = bh[tid];

    // --- Warp 0: gather 256 partials from L2 (fixed order -> deterministic)
    //     and shuffle-reduce so lane 0 holds the totals in registers. -------
    float r0 = 0.f, r1 = 0.f, r2 = 0.f;
    float bias00 = 0.f, bias01 = 0.f, bias02 = 0.f;
    if (tid == 0) {                        // issue bias LDGs early (DRAM)
        bias00 = bih0[0] + bhh0[0];
        bias01 = bih0[1] + bhh0[1];
        bias02 = bih0[2] + bhh0[2];
    }
    if (tid < 32) {
        const int base = tid * 8;
        #pragma unroll
        for (int k = 0; k < 8; ++k) {
            r0 += g_part[(base + k) * 3 + 0];
            r1 += g_part[(base + k) * 3 + 1];
            r2 += g_part[(base + k) * 3 + 2];
        }
        #pragma unroll
        for (int off = 16; off > 0; off >>= 1) {
            r0 += __shfl_down_sync(0xFFFFFFFFu, r0, off);
            r1 += __shfl_down_sync(0xFFFFFFFFu, r1, off);
            r2 += __shfl_down_sync(0xFFFFFFFFu, r2, off);
        }
    }
    __syncthreads();                       // sP/sWh/sBh ready

    // --- Serial 119-layer chain (1 thread). Hidden states -> GLOBAL g_H so
    //     STG cannot alias the shared weight loads; with the open register
    //     budget the distance-1 LDS.128 prefetch stays in registers and its
    //     latency hides under the tanh chain. ------------------------------
    if (tid == 0) {
        float h0 = tanh_scaled((r0 + bias00) * LOG2E_X2);
        float h1 = tanh_scaled((r1 + bias01) * LOG2E_X2);
        float h2 = tanh_scaled((r2 + bias02) * LOG2E_X2);
        g_H[0] = make_float4(h0, h1, h2, 0.f);

        float4 c0 = sP[0], c1 = sP[1], c2 = sP[2];
        #pragma unroll 7
        for (int l = 0; l < NCHAIN; ++l) {
            const float4 n0 = sP[(l + 1) * 3 + 0];
            const float4 n1 = sP[(l + 1) * 3 + 1];
            const float4 n2 = sP[(l + 1) * 3 + 2];
            // layout: w = {c0.x..c0.w, c1.x..c1.w, c2.x}, b = {c2.y,c2.z,c2.w}
            // (all pre-scaled by 2/ln2)
            const float t0 = fmaf(c0.x, h0, fmaf(c0.y, h1, fmaf(c0.z, h2, c2.y)));
            const float t1 = fmaf(c0.w, h0, fmaf(c1.x, h1, fmaf(c1.y, h2, c2.z)));
            const float t2 = fmaf(c1.z, h0, fmaf(c1.w, h1, fmaf(c2.x, h2, c2.w)));
            h0 = tanh_scaled(t0);
            h1 = tanh_scaled(t1);
            h2 = tanh_scaled(t2);
            g_H[l + 1] = make_float4(h0, h1, h2, 0.f);
            c0 = n0; c1 = n1; c2 = n2;
        }
    }
    __syncthreads();   // orders tid0's g_H stores before other threads' loads

    // --- Head: 54 parallel dot products; g_H is L1-hot on this SM. --------
    if (tid < HIDDEN * OUTPUTS) {
        const int j = tid / OUTPUTS;     // hidden index 0..2
        const int o = tid % OUTPUTS;     // output index 0..17
        float acc = sBh[o];
        const float* whrow = &sWh[o * LAYERS];
        #pragma unroll 8
        for (int l = 0; l < LAYERS; ++l) {
            const float4 hv = g_H[l];
            const float  hj = (j == 0) ? hv.x : ((j == 1) ? hv.y : hv.z);
            acc = fmaf(hj, whrow[l], acc);
        }
        out[j * OUTPUTS + o] = acc;      // row-major (3, 18)
    }
}

extern "C" void kernel_launch(void* const* d_in, const int* in_sizes, int n_in,
                              void* d_out, int out_size) {
    const float* x    = (const float*)d_in[0];
    const float* W0   = (const float*)d_in[1];
    const float* bih0 = (const float*)d_in[2];
    const float* bhh0 = (const float*)d_in[3];
    const float* Wl   = (const float*)d_in[4];
    const float* bil  = (const float*)d_in[5];
    const float* bhl  = (const float*)d_in[6];
    const float* Wh   = (const float*)d_in[7];
    const float* bh   = (const float*)d_in[8];
    float* out        = (float*)d_out;

    dqn_phase1_kernel<<<BLOCKS, THREADS>>>(x, W0);
    dqn_tail_kernel<<<1, THREADS>>>(bih0, bhh0, Wl, bil, bhl, Wh, bh, out);
}

// round 7
// speedup vs baseline: 1.8177x; 1.8177x over previous
#include <cuda_runtime.h>

// Problem constants (fixed by the reference).
#define N_IN      262144         // INPUT_LAYER
#define HIDDEN    3
#define LAYERS    120
#define NCHAIN    (LAYERS - 1)   // 119
#define OUTPUTS   18

#define BLOCKS    256
#define THREADS   256
// (N_IN/4) / (BLOCKS*THREADS) == 1 : exactly one float4 per thread per W0 row.

#define LOG2E_X2  2.8853900817779268f   // 2/ln(2)

// Scratch (no allocations allowed).
__device__ float    g_part[BLOCKS * 3];   // per-block partial dot products
__device__ unsigned g_count;              // zero at load; reset by block 0

// tanh from PRE-SCALED argument t = 2x/ln2:
//   e = 2^t = e^{2x};  tanh = 1 - 2/(e+1).
// Saturation-safe: e=inf -> 1; e=0 -> -1. Chain EX2+FADD+RCP+FMA ~= 40cyc.
__device__ __forceinline__ float tanh_scaled(float t) {
    float e, r;
    asm("ex2.approx.f32 %0, %1;" : "=f"(e) : "f"(t));
    float den = e + 1.0f;
    asm("rcp.approx.f32 %0, %1;" : "=f"(r) : "f"(den));
    return fmaf(-2.0f, r, 1.0f);
}

__global__ __launch_bounds__(THREADS)
void dqn_fused_kernel(const float* __restrict__ x,
                      const float* __restrict__ W0,     // (3, 262144)
                      const float* __restrict__ bih0,   // (3,)
                      const float* __restrict__ bhh0,   // (3,)
                      const float* __restrict__ Wl,     // (119, 3, 3)
                      const float* __restrict__ bil,    // (119, 3)
                      const float* __restrict__ bhl,    // (119, 3)
                      const float* __restrict__ Wh,     // (18, 120)
                      const float* __restrict__ bh,     // (18,)
                      float* __restrict__ out)          // (3, 18)
{
    __shared__ float wsum[3][8];

    const int tid = threadIdx.x;
    const int g   = blockIdx.x * THREADS + tid;

    // ---------------- Phase 1: partial dot products (HBM burst) -------------
    const float4 xv = reinterpret_cast<const float4*>(x)[g];
    const float4 a0 = reinterpret_cast<const float4*>(W0)[g];
    const float4 a1 = reinterpret_cast<const float4*>(W0 + N_IN)[g];
    const float4 a2 = reinterpret_cast<const float4*>(W0 + 2 * N_IN)[g];

    float s0 = a0.x * xv.x + a0.y * xv.y + a0.z * xv.z + a0.w * xv.w;
    float s1 = a1.x * xv.x + a1.y * xv.y + a1.z * xv.z + a1.w * xv.w;
    float s2 = a2.x * xv.x + a2.y * xv.y + a2.z * xv.z + a2.w * xv.w;

    #pragma unroll
    for (int off = 16; off > 0; off >>= 1) {
        s0 += __shfl_down_sync(0xFFFFFFFFu, s0, off);
        s1 += __shfl_down_sync(0xFFFFFFFFu, s1, off);
        s2 += __shfl_down_sync(0xFFFFFFFFu, s2, off);
    }
    const int wid = tid >> 5, lid = tid & 31;
    if (lid == 0) { wsum[0][wid] = s0; wsum[1][wid] = s1; wsum[2][wid] = s2; }
    __syncthreads();

    // ---------------- Non-tail blocks: publish partial and exit -------------
    if (blockIdx.x != 0) {
        if (tid == 0) {
            float b0 = 0.f, b1 = 0.f, b2 = 0.f;
            #pragma unroll
            for (int w = 0; w < 8; ++w) {
                b0 += wsum[0][w]; b1 += wsum[1][w]; b2 += wsum[2][w];
            }
            __stcg(&g_part[blockIdx.x * 3 + 0], b0);
            __stcg(&g_part[blockIdx.x * 3 + 1], b1);
            __stcg(&g_part[blockIdx.x * 3 + 2], b2);
            __threadfence();                 // release partials
            atomicAdd(&g_count, 1u);
        }
        return;
    }

    // ======================= Block 0: tail block =============================
    // sP2[(l-1)*3 + j] = float4{ W_l[j][0..2], b_ih+b_hh } * (2/ln2)  (rows of
    // layer l, one per lane). 3 pad rows so the in-loop prefetch never reads OOB.
    __shared__ float4 sP2[NCHAIN * 3 + 3];
    __shared__ float  sWhT[LAYERS * OUTPUTS];   // transposed head: [l][o]
    __shared__ float  sB0[3];                   // layer-0 fused bias, prescaled
    __shared__ float  sBh[OUTPUTS];

    if (tid == 0) {
        float b0 = 0.f, b1 = 0.f, b2 = 0.f;
        #pragma unroll
        for (int w = 0; w < 8; ++w) {
            b0 += wsum[0][w]; b1 += wsum[1][w]; b2 += wsum[2][w];
        }
        __stcg(&g_part[0], b0);
        __stcg(&g_part[1], b1);
        __stcg(&g_part[2], b2);
    }

    // Cooperative preload + repack (overlaps producers' phase 1).
    for (int i = tid; i < NCHAIN * 3; i += THREADS) {
        const int l = i / 3, j = i - l * 3;
        sP2[i] = make_float4(Wl[l * 9 + j * 3 + 0] * LOG2E_X2,
                             Wl[l * 9 + j * 3 + 1] * LOG2E_X2,
                             Wl[l * 9 + j * 3 + 2] * LOG2E_X2,
                             (bil[l * 3 + j] + bhl[l * 3 + j]) * LOG2E_X2);
    }
    if (tid < 3) {
        sP2[NCHAIN * 3 + tid] = make_float4(0.f, 0.f, 0.f, 0.f);
        sB0[tid] = (bih0[tid] + bhh0[tid]) * LOG2E_X2;
    }
    for (int i = tid; i < LAYERS * OUTPUTS; i += THREADS) {
        const int l = i / OUTPUTS, o = i - l * OUTPUTS;
        sWhT[i] = Wh[o * LAYERS + l];
    }
    if (tid < OUTPUTS) sBh[tid] = bh[tid];

    // Wait for all 255 producer blocks (acquire), then reset the counter.
    if (tid == 0) {
        unsigned v;
        do {
            asm volatile("ld.global.acquire.gpu.u32 %0, [%1];"
                         : "=r"(v) : "l"(&g_count));
        } while (v < BLOCKS - 1);
        g_count = 0;                         // ready for next graph replay
    }
    __syncthreads();   // smem ready; partials globally visible

    // ======== Warp 0 does EVERYTHING that remains (one warp, 32 lanes) ======
    if (tid < 32) {
        const int lane = tid;

        // --- Gather 256 partials (fixed order -> deterministic) + reduce ---
        float r0 = 0.f, r1 = 0.f, r2 = 0.f;
        {
            const int base = lane * 8;
            #pragma unroll
            for (int k = 0; k < 8; ++k) {
                r0 += __ldcg(&g_part[(base + k) * 3 + 0]);
                r1 += __ldcg(&g_part[(base + k) * 3 + 1]);
                r2 += __ldcg(&g_part[(base + k) * 3 + 2]);
            }
            #pragma unroll
            for (int off = 16; off > 0; off >>= 1) {
                r0 += __shfl_down_sync(0xFFFFFFFFu, r0, off);
                r1 += __shfl_down_sync(0xFFFFFFFFu, r1, off);
                r2 += __shfl_down_sync(0xFFFFFFFFu, r2, off);
            }
            r0 = __shfl_sync(0xFFFFFFFFu, r0, 0);   // broadcast totals
            r1 = __shfl_sync(0xFFFFFFFFu, r1, 0);
            r2 = __shfl_sync(0xFFFFFFFFu, r2, 0);
        }

        // --- Lane roles ---------------------------------------------------
        // Lanes 0..2: hidden component j = lane (lanes >=3 mirror lane 2's
        // computation harmlessly -> no predication on the critical path).
        // Lanes 3..29: head pairs p=lane-3 and p+27 accumulate in the shadow.
        const int jj = (lane < 3) ? lane : 2;
        const int p0 = (lane >= 3 && lane < 30) ? (lane - 3) : 0;
        const int p1 = p0 + 27;
        const int j0 = p0 / OUTPUTS, o0 = p0 - j0 * OUTPUTS;   // j0 in {0,1}
        const int j1 = p1 / OUTPUTS, o1 = p1 - j1 * OUTPUTS;   // j1 in {1,2}
        const float* wt0 = &sWhT[o0];
        const float* wt1 = &sWhT[o1];

        // --- Layer 0 ---
        const float myr = (lane == 0) ? r0 : ((lane == 1) ? r1 : r2);
        float h = tanh_scaled(fmaf(myr, LOG2E_X2, sB0[jj]));

        float acc0 = 0.f, acc1 = 0.f;
        const float4* wp = &sP2[jj];       // lane's weight row; +3 per layer
        float4 c = wp[0];                  // layer-1 row prefetch

        // --- 119 layers: shfl-broadcast h, accumulate head, step chain ----
        #pragma unroll 7
        for (int l = 1; l <= NCHAIN; ++l) {
            const float g0 = __shfl_sync(0xFFFFFFFFu, h, 0);
            const float g1 = __shfl_sync(0xFFFFFFFFu, h, 1);
            const float g2 = __shfl_sync(0xFFFFFFFFu, h, 2);
            // Head: layer l-1's H contributes (fills the dependency bubble).
            const float ga = (j0 == 0) ? g0 : g1;
            const float gb = (j1 == 1) ? g1 : g2;
            acc0 = fmaf(ga, wt0[(l - 1) * OUTPUTS], acc0);
            acc1 = fmaf(gb, wt1[(l - 1) * OUTPUTS], acc1);
            // Chain: this lane's component (weights pre-scaled by 2/ln2).
            const float t = fmaf(c.x, g0, fmaf(c.y, g1, fmaf(c.z, g2, c.w)));
            c = wp[l * 3];                 // prefetch next layer's row
            h = tanh_scaled(t);
        }

        // --- Final layer's H into the head, then write out ---------------
        const float g0 = __shfl_sync(0xFFFFFFFFu, h, 0);
        const float g1 = __shfl_sync(0xFFFFFFFFu, h, 1);
        const float g2 = __shfl_sync(0xFFFFFFFFu, h, 2);
        const float ga = (j0 == 0) ? g0 : g1;
        const float gb = (j1 == 1) ? g1 : g2;
        acc0 = fmaf(ga, wt0[NCHAIN * OUTPUTS], acc0);
        acc1 = fmaf(gb, wt1[NCHAIN * OUTPUTS], acc1);

        if (lane >= 3 && lane < 30) {
            out[j0 * OUTPUTS + o0] = acc0 + sBh[o0];
            out[j1 * OUTPUTS + o1] = acc1 + sBh[o1];
        }
    }
}

extern "C" void kernel_launch(void* const* d_in, const int* in_sizes, int n_in,
                              void* d_out, int out_size) {
    const float* x    = (const float*)d_in[0];
    const float* W0   = (const float*)d_in[1];
    const float* bih0 = (const float*)d_in[2];
    const float* bhh0 = (const float*)d_in[3];
    const float* Wl   = (const float*)d_in[4];
    const float* bil  = (const float*)d_in[5];
    const float* bhl  = (const float*)d_in[6];
    const float* Wh   = (const float*)d_in[7];
    const float* bh   = (const float*)d_in[8];
    float* out        = (float*)d_out;

    dqn_fused_kernel<<<BLOCKS, THREADS>>>(x, W0, bih0, bhh0,
                                          Wl, bil, bhl, Wh, bh, out);
}

// round 8
// speedup vs baseline: 1.8813x; 1.0350x over previous
#include <cuda_runtime.h>
#include <cstdint>

// Problem constants (fixed by the reference).
#define N_IN      262144         // INPUT_LAYER
#define HIDDEN    3
#define LAYERS    120
#define NCHAIN    (LAYERS - 1)   // 119
#define OUTPUTS   18

#define BLOCKS    128            // single wave on 148 SMs
#define THREADS   256
#define POS_PER_BLOCK 512        // float4 positions per block (65536/128)
#define CHUNK_BYTES   (POS_PER_BLOCK * 16)   // 8192 per array per block

#define LOG2E_X2  2.8853900817779268f   // 2/ln(2)

// Scratch (no allocations allowed).
__device__ float4   g_part4[BLOCKS];   // per-block partials {s0,s1,s2,0}
__device__ unsigned g_count;           // zero at load; reset by block 0

// tanh from PRE-SCALED argument t = 2x/ln2:
//   e = 2^t = e^{2x};  tanh = 1 - 2/(e+1).
// Saturation-safe: e=inf -> 1; e=0 -> -1. Chain EX2+FADD+RCP+FMA ~= 40cyc.
__device__ __forceinline__ float tanh_scaled(float t) {
    float e, r;
    asm("ex2.approx.f32 %0, %1;" : "=f"(e) : "f"(t));
    float den = e + 1.0f;
    asm("rcp.approx.f32 %0, %1;" : "=f"(r) : "f"(den));
    return fmaf(-2.0f, r, 1.0f);
}

__device__ __forceinline__ uint32_t smem_u32(const void* p) {
    uint32_t a;
    asm("{ .reg .u64 t; cvta.to.shared.u64 t, %1; cvt.u32.u64 %0, t; }"
        : "=r"(a) : "l"(p));
    return a;
}

__global__ __launch_bounds__(THREADS, 1)
void dqn_fused_kernel(const float* __restrict__ x,
                      const float* __restrict__ W0,     // (3, 262144)
                      const float* __restrict__ bih0,   // (3,)
                      const float* __restrict__ bhh0,   // (3,)
                      const float* __restrict__ Wl,     // (119, 3, 3)
                      const float* __restrict__ bil,    // (119, 3)
                      const float* __restrict__ bhl,    // (119, 3)
                      const float* __restrict__ Wh,     // (18, 120)
                      const float* __restrict__ bh,     // (18,)
                      float* __restrict__ out)          // (3, 18)
{
    // TMA staging (8KB x 4 = 32KB)
    __shared__ float4 sX [POS_PER_BLOCK];
    __shared__ float4 sW0[POS_PER_BLOCK];
    __shared__ float4 sW1[POS_PER_BLOCK];
    __shared__ float4 sW2[POS_PER_BLOCK];
    // Tail-block data
    __shared__ float4 sP2[NCHAIN * 3 + 3];       // 12 floats/layer + pad
    __shared__ float  sWhT[LAYERS * OUTPUTS];    // transposed head [l][o]
    __shared__ float  sB0[3];                    // layer-0 fused bias (scaled)
    __shared__ float  sBh[OUTPUTS];
    __shared__ float  wsum[3][8];
    __shared__ __align__(8) unsigned long long mbar;

    const int tid = threadIdx.x;
    const int bid = blockIdx.x;
    const uint32_t mb = smem_u32(&mbar);

    // ---- mbarrier init (fresh every launch -> phase 0) ---------------------
    if (tid == 0) {
        asm volatile("mbarrier.init.shared.b64 [%0], 1;" :: "r"(mb) : "memory");
    }
    __syncthreads();

    // ---- Issue 4 bulk copies: x slice + 3 W0-row slices --------------------
    if (tid == 0) {
        asm volatile("fence.proxy.async.shared::cta;" ::: "memory");
        asm volatile("mbarrier.arrive.expect_tx.shared.b64 _, [%0], %1;"
                     :: "r"(mb), "r"(4u * CHUNK_BYTES) : "memory");
        const char* srcx = (const char*)x              + (size_t)bid * CHUNK_BYTES;
        const char* s0   = (const char*)W0             + (size_t)bid * CHUNK_BYTES;
        const char* s1   = (const char*)(W0 + N_IN)    + (size_t)bid * CHUNK_BYTES;
        const char* s2   = (const char*)(W0 + 2*N_IN)  + (size_t)bid * CHUNK_BYTES;
        asm volatile("cp.async.bulk.shared::cluster.global.mbarrier::complete_tx::bytes [%0], [%1], %2, [%3];"
                     :: "r"(smem_u32(sX)),  "l"(srcx), "r"((uint32_t)CHUNK_BYTES), "r"(mb) : "memory");
        asm volatile("cp.async.bulk.shared::cluster.global.mbarrier::complete_tx::bytes [%0], [%1], %2, [%3];"
                     :: "r"(smem_u32(sW0)), "l"(s0),   "r"((uint32_t)CHUNK_BYTES), "r"(mb) : "memory");
        asm volatile("cp.async.bulk.shared::cluster.global.mbarrier::complete_tx::bytes [%0], [%1], %2, [%3];"
                     :: "r"(smem_u32(sW1)), "l"(s1),   "r"((uint32_t)CHUNK_BYTES), "r"(mb) : "memory");
        asm volatile("cp.async.bulk.shared::cluster.global.mbarrier::complete_tx::bytes [%0], [%1], %2, [%3];"
                     :: "r"(smem_u32(sW2)), "l"(s2),   "r"((uint32_t)CHUNK_BYTES), "r"(mb) : "memory");
    }

    // ---- Block 0: preload chain/head weights while the TMA flies -----------
    if (bid == 0) {
        float* sPf = reinterpret_cast<float*>(sP2);
        for (int i = tid; i < NCHAIN * 12; i += THREADS) {
            const int l = i / 12, k = i - l * 12;
            const float v = (k < 9) ? Wl[l * 9 + k]
                                    : bil[l * 3 + (k - 9)] + bhl[l * 3 + (k - 9)];
            sPf[i] = v * LOG2E_X2;
        }
        if (tid < 12) sPf[NCHAIN * 12 + tid] = 0.f;       // pad layer
        for (int i = tid; i < LAYERS * OUTPUTS; i += THREADS) {
            const int l = i / OUTPUTS, o = i - l * OUTPUTS;
            sWhT[i] = Wh[o * LAYERS + l];
        }
        if (tid < 3)       sB0[tid] = (bih0[tid] + bhh0[tid]) * LOG2E_X2;
        if (tid < OUTPUTS) sBh[tid] = bh[tid];
    }

    // ---- Wait for the bulk copies (acquire) --------------------------------
    asm volatile(
        "{\n\t"
        ".reg .pred p;\n\t"
        "W%=:\n\t"
        "mbarrier.try_wait.parity.acquire.cta.shared::cta.b64 p, [%0], 0;\n\t"
        "@!p bra W%=;\n\t"
        "}" :: "r"(mb) : "memory");

    // ---- Dot products out of shared (2 positions per thread) ---------------
    float s0, s1, s2;
    {
        const int p0 = tid, p1 = tid + THREADS;
        const float4 xa = sX[p0],  xb = sX[p1];
        const float4 a0 = sW0[p0], b0 = sW0[p1];
        const float4 a1 = sW1[p0], b1 = sW1[p1];
        const float4 a2 = sW2[p0], b2 = sW2[p1];
        s0 = a0.x*xa.x + a0.y*xa.y + a0.z*xa.z + a0.w*xa.w
           + b0.x*xb.x + b0.y*xb.y + b0.z*xb.z + b0.w*xb.w;
        s1 = a1.x*xa.x + a1.y*xa.y + a1.z*xa.z + a1.w*xa.w
           + b1.x*xb.x + b1.y*xb.y + b1.z*xb.z + b1.w*xb.w;
        s2 = a2.x*xa.x + a2.y*xa.y + a2.z*xa.z + a2.w*xa.w
           + b2.x*xb.x + b2.y*xb.y + b2.z*xb.z + b2.w*xb.w;
    }
    #pragma unroll
    for (int off = 16; off > 0; off >>= 1) {
        s0 += __shfl_down_sync(0xFFFFFFFFu, s0, off);
        s1 += __shfl_down_sync(0xFFFFFFFFu, s1, off);
        s2 += __shfl_down_sync(0xFFFFFFFFu, s2, off);
    }
    const int wid = tid >> 5, lid = tid & 31;
    if (lid == 0) { wsum[0][wid] = s0; wsum[1][wid] = s1; wsum[2][wid] = s2; }
    __syncthreads();

    if (tid == 0) {
        float b0 = 0.f, b1 = 0.f, b2 = 0.f;
        #pragma unroll
        for (int w = 0; w < 8; ++w) {
            b0 += wsum[0][w]; b1 += wsum[1][w]; b2 += wsum[2][w];
        }
        __stcg(&g_part4[bid], make_float4(b0, b1, b2, 0.f));
        // release-ordered increment (orders the partial store before it)
        unsigned one = 1u;
        asm volatile("red.release.gpu.global.add.u32 [%0], %1;"
                     :: "l"(&g_count), "r"(one) : "memory");
    }
    if (bid != 0) return;

    // ======================= Block 0: tail ==================================
    if (tid == 0) {
        unsigned v;
        do {
            asm volatile("ld.acquire.gpu.global.u32 %0, [%1];"
                         : "=r"(v) : "l"(&g_count));
        } while (v < BLOCKS);
        g_count = 0;                       // ready for next graph replay
    }
    __syncthreads();                       // smem weights + partials ready

    // ---- Warp 0: gather partials, run the chain + head ---------------------
    if (tid < 32) {
        const int lane = tid;

        // Gather 128 float4 partials, 4 per lane, fixed order (deterministic).
        float r0 = 0.f, r1 = 0.f, r2 = 0.f;
        #pragma unroll
        for (int k = 0; k < 4; ++k) {
            const float4 a = __ldcg(&g_part4[lane * 4 + k]);
            r0 += a.x; r1 += a.y; r2 += a.z;
        }
        #pragma unroll
        for (int off = 16; off > 0; off >>= 1) {
            r0 += __shfl_down_sync(0xFFFFFFFFu, r0, off);
            r1 += __shfl_down_sync(0xFFFFFFFFu, r1, off);
            r2 += __shfl_down_sync(0xFFFFFFFFu, r2, off);
        }
        r0 = __shfl_sync(0xFFFFFFFFu, r0, 0);
        r1 = __shfl_sync(0xFFFFFFFFu, r1, 0);
        r2 = __shfl_sync(0xFFFFFFFFu, r2, 0);

        // Per-lane head assignment: outputs p0=lane and p1=lane+27 (lanes<27).
        const int p0 = (lane < 27) ? lane : 0;
        const int j0 = p0 / OUTPUTS, o0 = p0 - j0 * OUTPUTS;   // j0 in {0,1}
        const int p1 = p0 + 27;
        const int j1 = p1 / OUTPUTS, o1 = p1 - j1 * OUTPUTS;   // j1 in {1,2}

        // Layer 0 (all lanes redundantly -> no cross-lane dependency at all).
        float h0 = tanh_scaled(fmaf(r0, LOG2E_X2, sB0[0]));
        float h1 = tanh_scaled(fmaf(r1, LOG2E_X2, sB0[1]));
        float h2 = tanh_scaled(fmaf(r2, LOG2E_X2, sB0[2]));

        float acc0 = 0.f, acc1 = 0.f;
        float4 c0 = sP2[0], c1 = sP2[1], c2 = sP2[2];

        // 119 layers. Every lane computes all 3 components (9 FMA + 3 tanh);
        // head FMAs ride in the tanh dependency bubble using LOCAL h values.
        // Packing: c0={w00,w01,w02,w10} c1={w11,w12,w20,w21} c2={w22,b0,b1,b2}
        #pragma unroll 7
        for (int l = 1; l <= NCHAIN; ++l) {
            // Head contribution of H[l-1] (current h regs).
            const float ha = (j0 == 0) ? h0 : h1;
            const float hb = (j1 == 1) ? h1 : h2;
            acc0 = fmaf(ha, sWhT[(l - 1) * OUTPUTS + o0], acc0);
            acc1 = fmaf(hb, sWhT[(l - 1) * OUTPUTS + o1], acc1);
            // Chain step (weights pre-scaled by 2/ln2).
            const float t0 = fmaf(c0.x, h0, fmaf(c0.y, h1, fmaf(c0.z, h2, c2.y)));
            const float t1 = fmaf(c0.w, h0, fmaf(c1.x, h1, fmaf(c1.y, h2, c2.z)));
            const float t2 = fmaf(c1.z, h0, fmaf(c1.w, h1, fmaf(c2.x, h2, c2.w)));
            c0 = sP2[l * 3 + 0];           // prefetch next layer (pad-safe)
            c1 = sP2[l * 3 + 1];
            c2 = sP2[l * 3 + 2];
            h0 = tanh_scaled(t0);
            h1 = tanh_scaled(t1);
            h2 = tanh_scaled(t2);
        }

        // Final layer's H, then write the two owned outputs.
        const float ha = (j0 == 0) ? h0 : h1;
        const float hb = (j1 == 1) ? h1 : h2;
        acc0 = fmaf(ha, sWhT[NCHAIN * OUTPUTS + o0], acc0);
        acc1 = fmaf(hb, sWhT[NCHAIN * OUTPUTS + o1], acc1);

        if (lane < 27) {
            out[j0 * OUTPUTS + o0] = acc0 + sBh[o0];
            out[j1 * OUTPUTS + o1] = acc1 + sBh[o1];
        }
    }
}

extern "C" void kernel_launch(void* const* d_in, const int* in_sizes, int n_in,
                              void* d_out, int out_size) {
    const float* x    = (const float*)d_in[0];
    const float* W0   = (const float*)d_in[1];
    const float* bih0 = (const float*)d_in[2];
    const float* bhh0 = (const float*)d_in[3];
    const float* Wl   = (const float*)d_in[4];
    const float* bil  = (const float*)d_in[5];
    const float* bhl  = (const float*)d_in[6];
    const float* Wh   = (const float*)d_in[7];
    const float* bh   = (const float*)d_in[8];
    float* out        = (float*)d_out;

    dqn_fused_kernel<<<BLOCKS, THREADS>>>(x, W0, bih0, bhh0,
                                          Wl, bil, bhl, Wh, bh, out);
}

// round 10
// speedup vs baseline: 2.5117x; 1.3351x over previous
#include <cuda_runtime.h>
#include <cstdint>

// Problem constants (fixed by the reference).
#define N_IN      262144         // INPUT_LAYER
#define HIDDEN    3
#define LAYERS    120
#define NCHAIN    (LAYERS - 1)   // 119
#define OUTPUTS   18

#define PROD      128            // producer blocks (blocks 1..128)
#define GRID      (PROD + 1)     // + tail block 0; single wave (129 <= 148)
#define THREADS   256
#define POS_PER_BLOCK 512        // float4 positions per producer (65536/128)
#define CHUNK_BYTES   (POS_PER_BLOCK * 16)   // 8192 per array per producer

// Scratch (no allocations allowed).
__device__ float4   g_part4[PROD];   // per-producer partials {s0,s1,s2,0}
__device__ unsigned g_count;         // zero at load; reset by tail block

// HW tanh: MUFU.TANH, ~16cyc (vs 40 for the ex2+rcp chain).
__device__ __forceinline__ float tanh_hw(float t) {
    float h;
    asm("tanh.approx.f32 %0, %1;" : "=f"(h) : "f"(t));
    return h;
}

__device__ __forceinline__ uint32_t smem_u32(const void* p) {
    uint32_t a;
    asm("{ .reg .u64 t; cvta.to.shared.u64 t, %1; cvt.u32.u64 %0, t; }"
        : "=r"(a) : "l"(p));
    return a;
}

__global__ __launch_bounds__(THREADS, 1)
void dqn_fused_kernel(const float* __restrict__ x,
                      const float* __restrict__ W0,     // (3, 262144)
                      const float* __restrict__ bih0,   // (3,)
                      const float* __restrict__ bhh0,   // (3,)
                      const float* __restrict__ Wl,     // (119, 3, 3)
                      const float* __restrict__ bil,    // (119, 3)
                      const float* __restrict__ bhl,    // (119, 3)
                      const float* __restrict__ Wh,     // (18, 120)
                      const float* __restrict__ bh,     // (18,)
                      float* __restrict__ out)          // (3, 18)
{
    // TMA staging for producers (8KB x 4 = 32KB)
    __shared__ float4 sX [POS_PER_BLOCK];
    __shared__ float4 sW0[POS_PER_BLOCK];
    __shared__ float4 sW1[POS_PER_BLOCK];
    __shared__ float4 sW2[POS_PER_BLOCK];
    // Tail-block data (unscaled weights; MUFU takes natural argument)
    __shared__ float4 sP2[NCHAIN * 3 + 3];       // 12 floats/layer + pad
    __shared__ float  sWhT[LAYERS * OUTPUTS];    // transposed head [l][o]
    __shared__ float  sB0[3];                    // layer-0 fused bias
    __shared__ float  sBh[OUTPUTS];
    __shared__ float  wsum[3][8];
    __shared__ __align__(8) unsigned long long mbar;

    const int tid = threadIdx.x;
    const int bid = blockIdx.x;

    // ======================= Tail block (bid == 0) ==========================
    if (bid == 0) {
        // ---- Preload + repack (fully overlaps producers' TMA phase) -------
        float* sPf = reinterpret_cast<float*>(sP2);
        for (int i = tid; i < NCHAIN * 12; i += THREADS) {
            const int l = i / 12, k = i - l * 12;
            sPf[i] = (k < 9) ? Wl[l * 9 + k]
                             : bil[l * 3 + (k - 9)] + bhl[l * 3 + (k - 9)];
        }
        if (tid < 12) sPf[NCHAIN * 12 + tid] = 0.f;       // pad layer
        for (int i = tid; i < LAYERS * OUTPUTS; i += THREADS) {
            const int l = i / OUTPUTS, o = i - l * OUTPUTS;
            sWhT[i] = Wh[o * LAYERS + l];
        }
        if (tid < 3)       sB0[tid] = bih0[tid] + bhh0[tid];
        if (tid < OUTPUTS) sBh[tid] = bh[tid];
        __syncthreads();                 // smem visible to warp 0
        if (tid >= 32) return;           // only warp 0 continues

        const int lane = tid;

        // ---- All 32 lanes spin on the counter (each gets acquire) ---------
        unsigned v;
        do {
            asm volatile("ld.acquire.gpu.global.u32 %0, [%1];"
                         : "=r"(v) : "l"(&g_count));
        } while (v < PROD);
        if (lane == 0) g_count = 0;      // ready for next graph replay

        // ---- Gather 128 partials, 4/lane, fixed order (deterministic) -----
        float r0 = 0.f, r1 = 0.f, r2 = 0.f;
        #pragma unroll
        for (int k = 0; k < 4; ++k) {
            const float4 a = __ldcg(&g_part4[lane * 4 + k]);
            r0 += a.x; r1 += a.y; r2 += a.z;
        }
        #pragma unroll
        for (int off = 16; off > 0; off >>= 1) {
            r0 += __shfl_down_sync(0xFFFFFFFFu, r0, off);
            r1 += __shfl_down_sync(0xFFFFFFFFu, r1, off);
            r2 += __shfl_down_sync(0xFFFFFFFFu, r2, off);
        }
        r0 = __shfl_sync(0xFFFFFFFFu, r0, 0);
        r1 = __shfl_sync(0xFFFFFFFFu, r1, 0);
        r2 = __shfl_sync(0xFFFFFFFFu, r2, 0);

        // Per-lane head outputs: p0=lane, p1=lane+27 (lanes < 27).
        const int p0 = (lane < 27) ? lane : 0;
        const int j0 = p0 / OUTPUTS, o0 = p0 - j0 * OUTPUTS;   // j0 in {0,1}
        const int p1 = p0 + 27;
        const int j1 = p1 / OUTPUTS, o1 = p1 - j1 * OUTPUTS;   // j1 in {1,2}

        // ---- Layer 0 (all lanes redundantly; no cross-lane dependency) ----
        float h0 = tanh_hw(r0 + sB0[0]);
        float h1 = tanh_hw(r1 + sB0[1]);
        float h2 = tanh_hw(r2 + sB0[2]);

        float acc0 = 0.f, acc1 = 0.f;
        float4 c0 = sP2[0], c1 = sP2[1], c2 = sP2[2];

        // ---- 119 layers @ ~28cyc: 3-FMA dot (12) + MUFU.TANH (16).
        // Prefetch + head FMAs ride in the dependency bubble.
        // Packing: c0={w00,w01,w02,w10} c1={w11,w12,w20,w21} c2={w22,b0,b1,b2}
        #pragma unroll 7
        for (int l = 1; l <= NCHAIN; ++l) {
            const float4 n0 = sP2[l * 3 + 0];     // next layer (pad-safe)
            const float4 n1 = sP2[l * 3 + 1];
            const float4 n2 = sP2[l * 3 + 2];
            // Head contribution of H[l-1] (current h regs).
            const float ha = (j0 == 0) ? h0 : h1;
            const float hb = (j1 == 1) ? h1 : h2;
            acc0 = fmaf(ha, sWhT[(l - 1) * OUTPUTS + o0], acc0);
            acc1 = fmaf(hb, sWhT[(l - 1) * OUTPUTS + o1], acc1);
            // Chain step.
            const float t0 = fmaf(c0.x, h0, fmaf(c0.y, h1, fmaf(c0.z, h2, c2.y)));
            const float t1 = fmaf(c0.w, h0, fmaf(c1.x, h1, fmaf(c1.y, h2, c2.z)));
            const float t2 = fmaf(c1.z, h0, fmaf(c1.w, h1, fmaf(c2.x, h2, c2.w)));
            h0 = tanh_hw(t0);
            h1 = tanh_hw(t1);
            h2 = tanh_hw(t2);
            c0 = n0; c1 = n1; c2 = n2;
        }

        // ---- Final layer's H into the head, then write -------------------
        const float ha = (j0 == 0) ? h0 : h1;
        const float hb = (j1 == 1) ? h1 : h2;
        acc0 = fmaf(ha, sWhT[NCHAIN * OUTPUTS + o0], acc0);
        acc1 = fmaf(hb, sWhT[NCHAIN * OUTPUTS + o1], acc1);

        if (lane < 27) {
            out[j0 * OUTPUTS + o0] = acc0 + sBh[o0];
            out[j1 * OUTPUTS + o1] = acc1 + sBh[o1];
        }
        return;
    }

    // ======================= Producer blocks (bid 1..128) ===================
    const int pid = bid - 1;
    const uint32_t mb = smem_u32(&mbar);

    if (tid == 0) {
        asm volatile("mbarrier.init.shared.b64 [%0], 1;" :: "r"(mb) : "memory");
    }
    __syncthreads();

    if (tid == 0) {
        asm volatile("fence.proxy.async.shared::cta;" ::: "memory");
        asm volatile("mbarrier.arrive.expect_tx.shared.b64 _, [%0], %1;"
                     :: "r"(mb), "r"(4u * CHUNK_BYTES) : "memory");
        const char* srcx = (const char*)x             + (size_t)pid * CHUNK_BYTES;
        const char* s0   = (const char*)W0            + (size_t)pid * CHUNK_BYTES;
        const char* s1   = (const char*)(W0 + N_IN)   + (size_t)pid * CHUNK_BYTES;
        const char* s2   = (const char*)(W0 + 2*N_IN) + (size_t)pid * CHUNK_BYTES;
        asm volatile("cp.async.bulk.shared::cluster.global.mbarrier::complete_tx::bytes [%0], [%1], %2, [%3];"
                     :: "r"(smem_u32(sX)),  "l"(srcx), "r"((uint32_t)CHUNK_BYTES), "r"(mb) : "memory");
        asm volatile("cp.async.bulk.shared::cluster.global.mbarrier::complete_tx::bytes [%0], [%1], %2, [%3];"
                     :: "r"(smem_u32(sW0)), "l"(s0),   "r"((uint32_t)CHUNK_BYTES), "r"(mb) : "memory");
        asm volatile("cp.async.bulk.shared::cluster.global.mbarrier::complete_tx::bytes [%0], [%1], %2, [%3];"
                     :: "r"(smem_u32(sW1)), "l"(s1),   "r"((uint32_t)CHUNK_BYTES), "r"(mb) : "memory");
        asm volatile("cp.async.bulk.shared::cluster.global.mbarrier::complete_tx::bytes [%0], [%1], %2, [%3];"
                     :: "r"(smem_u32(sW2)), "l"(s2),   "r"((uint32_t)CHUNK_BYTES), "r"(mb) : "memory");
    }

    // Wait for the bulk copies (acquire).
    asm volatile(
        "{\n\t"
        ".reg .pred p;\n\t"
        "W%=:\n\t"
        "mbarrier.try_wait.parity.acquire.cta.shared::cta.b64 p, [%0], 0;\n\t"
        "@!p bra W%=;\n\t"
        "}" :: "r"(mb) : "memory");

    // Dot products out of shared (2 positions per thread).
    float s0, s1, s2;
    {
        const int q0 = tid, q1 = tid + THREADS;
        const float4 xa = sX[q0],  xb = sX[q1];
        const float4 a0 = sW0[q0], b0 = sW0[q1];
        const float4 a1 = sW1[q0], b1 = sW1[q1];
        const float4 a2 = sW2[q0], b2 = sW2[q1];
        s0 = a0.x*xa.x + a0.y*xa.y + a0.z*xa.z + a0.w*xa.w
           + b0.x*xb.x + b0.y*xb.y + b0.z*xb.z + b0.w*xb.w;
        s1 = a1.x*xa.x + a1.y*xa.y + a1.z*xa.z + a1.w*xa.w
           + b1.x*xb.x + b1.y*xb.y + b1.z*xb.z + b1.w*xb.w;
        s2 = a2.x*xa.x + a2.y*xa.y + a2.z*xa.z + a2.w*xa.w
           + b2.x*xb.x + b2.y*xb.y + b2.z*xb.z + b2.w*xb.w;
    }
    #pragma unroll
    for (int off = 16; off > 0; off >>= 1) {
        s0 += __shfl_down_sync(0xFFFFFFFFu, s0, off);
        s1 += __shfl_down_sync(0xFFFFFFFFu, s1, off);
        s2 += __shfl_down_sync(0xFFFFFFFFu, s2, off);
    }
    const int wid = tid >> 5, lid = tid & 31;
    if (lid == 0) { wsum[0][wid] = s0; wsum[1][wid] = s1; wsum[2][wid] = s2; }
    __syncthreads();

    if (tid == 0) {
        float b0 = 0.f, b1 = 0.f, b2 = 0.f;
        #pragma unroll
        for (int w = 0; w < 8; ++w) {
            b0 += wsum[0][w]; b1 += wsum[1][w]; b2 += wsum[2][w];
        }
        __stcg(&g_part4[pid], make_float4(b0, b1, b2, 0.f));
        unsigned one = 1u;
        asm volatile("red.release.gpu.global.add.u32 [%0], %1;"
                     :: "l"(&g_count), "r"(one) : "memory");
    }
}

extern "C" void kernel_launch(void* const* d_in, const int* in_sizes, int n_in,
                              void* d_out, int out_size) {
    const float* x    = (const float*)d_in[0];
    const float* W0   = (const float*)d_in[1];
    const float* bih0 = (const float*)d_in[2];
    const float* bhh0 = (const float*)d_in[3];
    const float* Wl   = (const float*)d_in[4];
    const float* bil  = (const float*)d_in[5];
    const float* bhl  = (const float*)d_in[6];
    const float* Wh   = (const float*)d_in[7];
    const float* bh   = (const float*)d_in[8];
    float* out        = (float*)d_out;

    dqn_fused_kernel<<<GRID, THREADS>>>(x, W0, bih0, bhh0,
                                        Wl, bil, bhl, Wh, bh, out);
}